// round 16
// baseline (speedup 1.0000x reference)
#include <cuda_runtime.h>
#include <cuda_bf16.h>
#include <stdint.h>

// Problem:
//   x:   (B, S) token ids in [0, V)   (B=512, S=1024, V=50257)
//   idf: (V,) fp32
//   out: (B, V) fp32 = (tf * idf) / rowsum(tf * idf)
//
// R16 design:
//   - chunked driver memset (8 chunks, ~2.1 us each, write-roofline) on sM
//   - fused row kernel on sS: one block per row -> vectorized 4-token/thread
//     loads, idf gathers, block-reduce normalizer, then 4 independent
//     no-return atomicAdds (duplicates accumulate to cnt*idf*inv_n).
//   - scatter chunk c waits only on memset chunk c; designed to run faster
//     than one memset chunk so the memset stream is the sole critical path.

#define NTH 256
#define TPT 4
#define NCHUNK 8

__inline__ __device__ float warp_reduce_sum(float v) {
    #pragma unroll
    for (int o = 16; o > 0; o >>= 1)
        v += __shfl_xor_sync(0xffffffffu, v, o);
    return v;
}

__inline__ __device__ bool detect_i64(const int* xi) {
    // little-endian int64 < 2^31 has zero high words at odd 32-bit indices;
    // P[4 real int32 tokens all == 0] ~ (1/50257)^4 — negligible.
    return (xi[1] == 0) & (xi[3] == 0) & (xi[5] == 0) & (xi[7] == 0);
}

__global__ __launch_bounds__(NTH)
void tfidf_row_kernel(const void* __restrict__ xv,
                      const float* __restrict__ idf,
                      float* __restrict__ out,
                      int row0, int seq, int vocab) {
    const int row = row0 + blockIdx.x;
    const int tid = threadIdx.x;

    const int* xi = (const int*)xv;
    const bool is64 = detect_i64(xi);

    int   tok[TPT];
    float w[TPT];
    float partial = 0.0f;
    int   nmine = 0;

    if (seq == NTH * TPT) {
        // fast path: 4 consecutive tokens per thread, vectorized loads
        if (is64) {
            const ulonglong2* p =
                (const ulonglong2*)((const long long*)xv + (size_t)row * seq);
            ulonglong2 a = p[tid * 2];
            ulonglong2 b = p[tid * 2 + 1];
            tok[0] = (int)a.x; tok[1] = (int)a.y;
            tok[2] = (int)b.x; tok[3] = (int)b.y;
        } else {
            const int4* p = (const int4*)(xi + (size_t)row * seq);
            int4 a = p[tid];
            tok[0] = a.x; tok[1] = a.y; tok[2] = a.z; tok[3] = a.w;
        }
        nmine = TPT;
        #pragma unroll
        for (int i = 0; i < TPT; i++) {
            w[i] = __ldg(idf + tok[i]);
            partial += w[i];
        }
    } else {
        // generic strided fallback
        const long long* x64 = (const long long*)xv + (size_t)row * seq;
        const int*       x32 = xi + (size_t)row * seq;
        for (int s = tid; s < seq && nmine < TPT; s += NTH) {
            int t = is64 ? (int)x64[s] : x32[s];
            tok[nmine] = t;
            w[nmine]   = __ldg(idf + t);
            partial   += w[nmine];
            nmine++;
        }
        // (seq > NTH*TPT unsupported by fallback register budget; problem
        //  shape is S=1024 = NTH*TPT so the fast path is the real path)
        for (int s = tid + NTH * TPT; s < seq; s += NTH)
            partial += __ldg(idf + (is64 ? (int)x64[s] : x32[s]));
    }

    // block reduction -> inv_n (8 warps)
    __shared__ float red[NTH / 32];
    __shared__ float inv_n_sh;
    float ws = warp_reduce_sum(partial);
    const int lane = tid & 31, warp = tid >> 5;
    if (lane == 0) red[warp] = ws;
    __syncthreads();
    if (warp == 0) {
        float v = (lane < (NTH / 32)) ? red[lane] : 0.0f;
        v = warp_reduce_sum(v);
        if (lane == 0) inv_n_sh = 1.0f / v;
    }
    __syncthreads();
    const float inv_n = inv_n_sh;

    // 4 independent no-return atomics; duplicates within the row accumulate
    // exactly to cnt * idf * inv_n (identical addends)
    float* orow = out + (size_t)row * vocab;
    #pragma unroll
    for (int i = 0; i < TPT; i++)
        if (i < nmine)
            atomicAdd(orow + tok[i], w[i] * inv_n);
}

extern "C" void kernel_launch(void* const* d_in, const int* in_sizes, int n_in,
                              void* d_out, int out_size) {
    (void)n_in;
    const void*  x   = d_in[0];                 // (B, S) tokens
    const float* idf = (const float*)d_in[1];   // (V,) fp32
    float*       out = (float*)d_out;           // (B, V) fp32

    const int vocab = in_sizes[1];              // V
    const int batch = out_size / vocab;         // B
    const int seq   = in_sizes[0] / batch;      // S

    // one-time stream/event setup — correctness call, OUTSIDE graph capture
    static bool init = false;
    static cudaStream_t sM, sS;
    static cudaEvent_t evFork, evM[NCHUNK], evJoinM, evJoinS;
    if (!init) {
        cudaStreamCreateWithFlags(&sM, cudaStreamNonBlocking);
        cudaStreamCreateWithFlags(&sS, cudaStreamNonBlocking);
        cudaEventCreateWithFlags(&evFork, cudaEventDisableTiming);
        for (int c = 0; c < NCHUNK; c++)
            cudaEventCreateWithFlags(&evM[c], cudaEventDisableTiming);
        cudaEventCreateWithFlags(&evJoinM, cudaEventDisableTiming);
        cudaEventCreateWithFlags(&evJoinS, cudaEventDisableTiming);
        init = true;
    }

    // fork
    cudaEventRecord(evFork, 0);
    cudaStreamWaitEvent(sM, evFork, 0);
    cudaStreamWaitEvent(sS, evFork, 0);

    // pipelined memset (sM) -> fused row kernel (sS), chunk by chunk
    const int rpc = (batch + NCHUNK - 1) / NCHUNK;
    for (int c = 0; c < NCHUNK; c++) {
        const int row0  = c * rpc;
        const int nrows = (row0 + rpc <= batch) ? rpc : (batch - row0);
        if (nrows <= 0) break;
        cudaMemsetAsync(out + (size_t)row0 * vocab, 0,
                        (size_t)nrows * vocab * sizeof(float), sM);
        cudaEventRecord(evM[c], sM);
        cudaStreamWaitEvent(sS, evM[c], 0);
        tfidf_row_kernel<<<nrows, NTH, 0, sS>>>(x, idf, out, row0, seq, vocab);
    }

    // join
    cudaEventRecord(evJoinM, sM);
    cudaEventRecord(evJoinS, sS);
    cudaStreamWaitEvent(0, evJoinM, 0);
    cudaStreamWaitEvent(0, evJoinS, 0);
}

// round 17
// speedup vs baseline: 1.1656x; 1.1656x over previous
#include <cuda_runtime.h>
#include <cuda_bf16.h>
#include <stdint.h>

// Problem:
//   x:   (B, S) token ids in [0, V)   (B=512, S=1024, V=50257)
//   idf: (V,) fp32
//   out: (B, V) fp32 = (tf * idf) / rowsum(tf * idf)
//
// R17 design (floor = 17.2us DRAM-bound memset; hide everything else):
//   - norm kernel (rowsum via idf gathers -> g_inv_n[]) on scatter stream,
//     overlapping memset chunk 0.
//   - driver memset chunked {5,5,4,2}/16 of B on stream sM (descending so
//     the post-final-memset scatter tail is tiny).
//   - scatter: flat 2D grid, ONE thread per token, no divide, no block
//     reduce. atomicAdd(out[row,tok], idf[tok]*inv_n[row]); duplicates
//     accumulate exactly to cnt*idf*inv_n.

#define NTH 256
#define NCHUNK 4
#define MAX_B 4096

__device__ float g_inv_n[MAX_B];

__inline__ __device__ float warp_reduce_sum(float v) {
    #pragma unroll
    for (int o = 16; o > 0; o >>= 1)
        v += __shfl_xor_sync(0xffffffffu, v, o);
    return v;
}

__inline__ __device__ bool detect_i64(const int* xi) {
    // little-endian int64 < 2^31 has zero high words at odd 32-bit indices;
    // P[4 real int32 tokens all == 0] ~ (1/50257)^4 — negligible. The four
    // words are L1-broadcast after first touch.
    return (xi[1] == 0) & (xi[3] == 0) & (xi[5] == 0) & (xi[7] == 0);
}

__global__ __launch_bounds__(NTH)
void row_norm_kernel(const void* __restrict__ xv,
                     const float* __restrict__ idf, int seq) {
    const int row = blockIdx.x;
    const int tid = threadIdx.x;
    const int* xi = (const int*)xv;
    const bool is64 = detect_i64(xi);
    const long long* x64 = (const long long*)xv + (size_t)row * seq;
    const int*       x32 = xi + (size_t)row * seq;

    float partial = 0.0f;
    for (int s = tid; s < seq; s += NTH) {
        int tok = is64 ? (int)x64[s] : x32[s];
        partial += __ldg(idf + tok);
    }

    __shared__ float red[NTH / 32];
    float ws = warp_reduce_sum(partial);
    const int lane = tid & 31, warp = tid >> 5;
    if (lane == 0) red[warp] = ws;
    __syncthreads();
    if (warp == 0) {
        float v = (lane < (NTH / 32)) ? red[lane] : 0.0f;
        v = warp_reduce_sum(v);
        if (lane == 0) g_inv_n[row] = 1.0f / v;
    }
}

// 2D grid: x covers the sequence, y covers rows of this chunk.
__global__ __launch_bounds__(NTH)
void scatter_kernel(const void* __restrict__ xv,
                    const float* __restrict__ idf,
                    float* __restrict__ out,
                    int row0, int seq, int vocab) {
    const int s   = blockIdx.x * NTH + threadIdx.x;
    const int row = row0 + blockIdx.y;
    if (s >= seq) return;

    const int* xi = (const int*)xv;
    const bool is64 = detect_i64(xi);
    const int tok = is64 ? (int)((const long long*)xv)[(size_t)row * seq + s]
                         : xi[(size_t)row * seq + s];

    // no-return fp32 atomic; duplicates within the row add identical values
    atomicAdd(out + (size_t)row * vocab + tok,
              __ldg(idf + tok) * g_inv_n[row]);
}

extern "C" void kernel_launch(void* const* d_in, const int* in_sizes, int n_in,
                              void* d_out, int out_size) {
    (void)n_in;
    const void*  x   = d_in[0];                 // (B, S) tokens
    const float* idf = (const float*)d_in[1];   // (V,) fp32
    float*       out = (float*)d_out;           // (B, V) fp32

    const int vocab = in_sizes[1];              // V
    const int batch = out_size / vocab;         // B
    const int seq   = in_sizes[0] / batch;      // S

    // one-time stream/event setup — correctness call, OUTSIDE graph capture;
    // no device memory is allocated here.
    static bool init = false;
    static cudaStream_t sM, sS;
    static cudaEvent_t evFork, evM[NCHUNK], evJoinM, evJoinS;
    if (!init) {
        cudaStreamCreateWithFlags(&sM, cudaStreamNonBlocking);
        cudaStreamCreateWithFlags(&sS, cudaStreamNonBlocking);
        cudaEventCreateWithFlags(&evFork, cudaEventDisableTiming);
        for (int c = 0; c < NCHUNK; c++)
            cudaEventCreateWithFlags(&evM[c], cudaEventDisableTiming);
        cudaEventCreateWithFlags(&evJoinM, cudaEventDisableTiming);
        cudaEventCreateWithFlags(&evJoinS, cudaEventDisableTiming);
        init = true;
    }

    // descending chunk sizes: weights {5,5,4,2}/16 — small final chunk
    // minimizes the serial tail after the last memset.
    int nrows_c[NCHUNK];
    {
        const int w[NCHUNK] = {5, 5, 4, 2};
        int acc = 0;
        for (int c = 0; c < NCHUNK - 1; c++) {
            nrows_c[c] = (int)(((long long)batch * w[c]) / 16);
            if (nrows_c[c] < 1) nrows_c[c] = (batch - acc > 0) ? 1 : 0;
            acc += nrows_c[c];
        }
        nrows_c[NCHUNK - 1] = batch - acc;
    }

    // fork both worker streams off the launch stream
    cudaEventRecord(evFork, 0);
    cudaStreamWaitEvent(sM, evFork, 0);
    cudaStreamWaitEvent(sS, evFork, 0);

    // normalizers on sS (overlaps memset chunk 0); stream order guarantees
    // g_inv_n is written before any scatter on sS reads it.
    row_norm_kernel<<<batch, NTH, 0, sS>>>(x, idf, seq);

    const int sblocks = (seq + NTH - 1) / NTH;
    int row0 = 0;
    for (int c = 0; c < NCHUNK; c++) {
        const int nrows = nrows_c[c];
        if (nrows <= 0) continue;
        cudaMemsetAsync(out + (size_t)row0 * vocab, 0,
                        (size_t)nrows * vocab * sizeof(float), sM);
        cudaEventRecord(evM[c], sM);
        cudaStreamWaitEvent(sS, evM[c], 0);
        dim3 grid(sblocks, nrows);
        scatter_kernel<<<grid, NTH, 0, sS>>>(x, idf, out, row0, seq, vocab);
        row0 += nrows;
    }

    // join
    cudaEventRecord(evJoinM, sM);
    cudaEventRecord(evJoinS, sS);
    cudaStreamWaitEvent(0, evJoinM, 0);
    cudaStreamWaitEvent(0, evJoinS, 0);
}